// round 15
// baseline (speedup 1.0000x reference)
#include <cuda_runtime.h>

#define NCH 27
#define HH 64
#define WW 64
#define OC 32
#define NB 2
#define PITCHW 68    // 32-bit words per tile row = 34 interleaved pairs
#define PITCHP 34    // ull pairs per tile row

typedef unsigned long long ull;

__device__ __forceinline__ ull addp(ull a, ull b) {
    ull r; asm("add.rn.f32x2 %0, %1, %2;" : "=l"(r) : "l"(a), "l"(b)); return r;
}
__device__ __forceinline__ ull mulp(ull a, ull b) {
    ull r; asm("mul.rn.f32x2 %0, %1, %2;" : "=l"(r) : "l"(a), "l"(b)); return r;
}
__device__ __forceinline__ ull fmap(ull a, ull b, ull c) {
    ull r; asm("fma.rn.f32x2 %0, %1, %2, %3;" : "=l"(r) : "l"(a), "l"(b), "l"(c)); return r;
}
__device__ __forceinline__ ull pack2u(unsigned lo, unsigned hi) {
    ull r; asm("mov.b64 %0, {%1, %2};" : "=l"(r) : "r"(lo), "r"(hi)); return r;
}
__device__ __forceinline__ void unpack2(ull v, unsigned& lo, unsigned& hi) {
    asm("mov.b64 {%0, %1}, %2;" : "=r"(lo), "=r"(hi) : "l"(v));
}

// packed maj3 on both lanes: 0.5*(a+b+c) - 0.5*(a*b*c)
__device__ __forceinline__ ull maj3p(ull a, ull b, ull c, ull h2, ull nh2) {
    ull s = addp(addp(a, b), c);
    ull q = mulp(mulp(a, b), c);
    return fmap(q, nh2, mulp(s, h2));
}

// grid (HH, OC/4, NB), 128 threads = 32 pixel-pairs x 4 ocs.
// STRIDED pixel pairing: thread computes output cols (p, p+32), lanes packed f32x2.
// Tile stored pre-interleaved: P[row][i] = (x[i-1], x[i+31]) as ull, i = 0..33.
// Leaf operands X0..X2 = P[p..p+2]: aligned LDS.64, NO pack/unpack in hot loop.
// Tile loaded once; duplicated half-weights phased 27 rows at a time (small smem).
__global__ __launch_bounds__(128, 6) void sconv_kernel(const float* __restrict__ x,
                                                       const float* __restrict__ wraw,
                                                       float* __restrict__ out) {
    __shared__ __align__(16) float  tf[81 * PITCHW];   // interleaved pair tile, 22.0KB
    __shared__ __align__(16) float2 wdup[4 * 27 * 4];  // phase weights: [ol][rl][4] dup pairs, 3.4KB

    const int h   = blockIdx.x;
    const int ocg = blockIdx.y;
    const int n   = blockIdx.z;
    const int tid = threadIdx.x;

    const int p  = tid & 31;   // pair index: output cols p, p+32
    const int ol = tid >> 5;   // oc within group (uniform per warp -> broadcast LDS)

    // edge words: P[row][0].lane0 = x[-1] = 0, P[row][33].lane1 = x[64] = 0
    for (int i = tid; i < 162; i += 128) {
        int row = i >> 1;
        tf[row * PITCHW + ((i & 1) ? 67 : 0)] = 0.0f;
    }

    // interior: each loaded x[col] feeds lane0 of P[col+1] (col<=32)
    // and lane1 of P[col-31] (col>=31)
    {
        const float* xb = x + (size_t)n * NCH * HH * WW;
        const int col = tid & 63;
#pragma unroll 4
        for (int row = tid >> 6; row < 81; row += 2) {
            int c  = row / 3;
            int r  = row - 3 * c;
            int gh = h + r - 1;
            float v = 0.0f;
            if ((unsigned)gh < (unsigned)HH)
                v = xb[c * (HH * WW) + gh * WW + col];
            float* trow = tf + row * PITCHW;
            if (col <= 32) trow[2 * (col + 1)]      = v;  // lane0 of P[col+1]
            if (col >= 31) trow[2 * (col - 31) + 1] = v;  // lane1 of P[col-31]
        }
    }

    const ull* t8 = reinterpret_cast<const ull*>(tf);
    const ulonglong2* wp = reinterpret_cast<const ulonglong2*>(wdup) + ol * 54;

    const ull h2  = pack2u(0x3F000000u, 0x3F000000u);   // (0.5, 0.5)
    const ull nh2 = pack2u(0xBF000000u, 0xBF000000u);   // (-0.5, -0.5)

    ull a3[3];

    for (int g3 = 0; g3 < 3; g3++) {
        __syncthreads();   // g3=0: tile ready; g3>0: prev-phase wdup consumers done

        // duplicated half-weights for rows 27*g3 .. 27*g3+26 (one iter, threads >=108 idle)
        for (int i = tid; i < 108; i += 128) {
            int o  = i / 27;
            int rl = i - o * 27;
            const float* pw = wraw + ((ocg * 4 + o) * 81 + 27 * g3 + rl) * 3;
            float a = pw[0], b = pw[1], c = pw[2];
            float2* d = &wdup[i * 4];
            d[0] = make_float2(0.5f * a, 0.5f * a);
            d[1] = make_float2(0.5f * b, 0.5f * b);
            d[2] = make_float2(0.5f * c, 0.5f * c);
            float t = -0.5f * a * b * c;
            d[3] = make_float2(t, t);
        }
        __syncthreads();

        ull a9[3];
#pragma unroll
        for (int g9 = 0; g9 < 3; g9++) {
            ull ch[3];
#pragma unroll
            for (int cc = 0; cc < 3; cc++) {
                const int cp = g9 * 3 + cc;        // channel within phase
                ull rr[3];
#pragma unroll
                for (int ki = 0; ki < 3; ki++) {
                    const int rl  = cp * 3 + ki;   // row within phase (weights)
                    const int row = 27 * g3 + rl;  // global tile row
                    const ull* pr = t8 + row * PITCHP;
                    ull X0 = pr[p];                // (x[p-1] | x[p+31])
                    ull X1 = pr[p + 1];            // (x[p]   | x[p+32])
                    ull X2 = pr[p + 2];            // (x[p+1] | x[p+33])

                    ulonglong2 W01 = wp[rl * 2 + 0];   // (w0/2)x2, (w1/2)x2
                    ulonglong2 W23 = wp[rl * 2 + 1];   // (w2/2)x2, (-w0w1w2/2)x2

                    ull s = mulp(X0, W01.x);
                    s = fmap(X1, W01.y, s);
                    s = fmap(X2, W23.x, s);
                    ull P = mulp(mulp(X0, X1), X2);
                    rr[ki] = fmap(P, W23.y, s);        // folded leaf maj3
                }
                ch[cc] = maj3p(rr[0], rr[1], rr[2], h2, nh2);
            }
            a9[g9] = maj3p(ch[0], ch[1], ch[2], h2, nh2);
        }
        a3[g3] = maj3p(a9[0], a9[1], a9[2], h2, nh2);
    }

    ull res = maj3p(a3[0], a3[1], a3[2], h2, nh2);
    unsigned rlo, rhi;
    unpack2(res, rlo, rhi);

    const int oc = ocg * 4 + ol;
    float* ob = out + (((size_t)n * OC + oc) * HH + h) * WW;
    ob[p]      = __uint_as_float(rlo);   // output col p
    ob[p + 32] = __uint_as_float(rhi);   // output col p+32
}

extern "C" void kernel_launch(void* const* d_in, const int* in_sizes, int n_in,
                              void* d_out, int out_size) {
    const float* x = (const float*)d_in[0];
    const float* w = (const float*)d_in[1];
    float* out = (float*)d_out;

    dim3 grid(HH, OC / 4, NB);
    sconv_kernel<<<grid, 128>>>(x, w, out);
}

// round 16
// speedup vs baseline: 2.2315x; 2.2315x over previous
#include <cuda_runtime.h>

#define NCH 27
#define HH 64
#define WW 64
#define OC 32
#define NB 2
#define PITCH 68   // tile row pitch (floats); 64 data + halo + pad, keeps 2p offsets 8B-aligned

typedef unsigned long long ull;

__device__ __forceinline__ ull addp(ull a, ull b) {
    ull r; asm("add.rn.f32x2 %0, %1, %2;" : "=l"(r) : "l"(a), "l"(b)); return r;
}
__device__ __forceinline__ ull mulp(ull a, ull b) {
    ull r; asm("mul.rn.f32x2 %0, %1, %2;" : "=l"(r) : "l"(a), "l"(b)); return r;
}
__device__ __forceinline__ ull fmap(ull a, ull b, ull c) {
    ull r; asm("fma.rn.f32x2 %0, %1, %2, %3;" : "=l"(r) : "l"(a), "l"(b), "l"(c)); return r;
}
__device__ __forceinline__ ull pack2u(unsigned lo, unsigned hi) {
    ull r; asm("mov.b64 %0, {%1, %2};" : "=l"(r) : "r"(lo), "r"(hi)); return r;
}
__device__ __forceinline__ ull pack2f(float lo, float hi) {
    return pack2u(__float_as_uint(lo), __float_as_uint(hi));
}

// packed maj3 on both lanes: 0.5*(a+b+c) - 0.5*(a*b*c)
__device__ __forceinline__ ull maj3p(ull a, ull b, ull c, ull h2, ull nh2) {
    ull s = addp(addp(a, b), c);
    ull q = mulp(mulp(a, b), c);
    return fmap(q, nh2, mulp(s, h2));
}

// grid (HH, OC/4, NB), 128 threads.
// thread -> pixel pair p = tid&31 (cols 2p, 2p+1), oc_local = tid>>5 (0..3).
// Leaves scalar (shares x-triple products between pixels); tree packed f32x2
// (lanes = the two pixels). Structure otherwise identical to the 16.9us kernel.
__global__ __launch_bounds__(128, 7) void sconv_kernel(const float* __restrict__ x,
                                                       const float* __restrict__ wraw,
                                                       float* __restrict__ out) {
    __shared__ __align__(16) float  tile[81 * PITCH];   // [row=c*3+r][col 0..65], col0/col65 = zero halo
    __shared__ float4 wsh[4 * 81];                      // packed half-weights for 4 ocs

    const int h   = blockIdx.x;
    const int ocg = blockIdx.y;
    const int n   = blockIdx.z;
    const int tid = threadIdx.x;

    // pack weights for the block's 4 ocs: {w0/2, w1/2, w2/2, w0w1w2/2}
    for (int i = tid; i < 4 * 81; i += 128) {
        int ol2 = i / 81;
        int win = i - ol2 * 81;
        const float* pw = wraw + (ocg * 4 + ol2) * 243 + win * 3;
        float a = pw[0], b = pw[1], c = pw[2];
        wsh[i] = make_float4(0.5f * a, 0.5f * b, 0.5f * c, 0.5f * a * b * c);
    }

    // halo columns (gw=-1, gw=64) are always outside the image -> zero
    for (int i = tid; i < 162; i += 128) {
        int row = i >> 1;
        tile[row * PITCH + ((i & 1) ? 65 : 0)] = 0.0f;
    }

    // interior: 81 rows x 64 cols
    {
        const float* xb = x + (size_t)n * NCH * HH * WW;
        const int col = tid & 63;
#pragma unroll 4
        for (int row = tid >> 6; row < 81; row += 2) {
            int c  = row / 3;
            int r  = row - 3 * c;
            int gh = h + r - 1;
            float v = 0.0f;
            if ((unsigned)gh < (unsigned)HH)
                v = xb[c * (HH * WW) + gh * WW + col];
            tile[row * PITCH + 1 + col] = v;
        }
    }
    __syncthreads();

    const int p  = tid & 31;   // pixel pair: output cols 2p, 2p+1
    const int ol = tid >> 5;   // oc within group (uniform per warp -> broadcast weight LDS)
    const float2* t2 = reinterpret_cast<const float2*>(tile);
    const float4* wp = wsh + ol * 81;

    const ull h2  = pack2u(0x3F000000u, 0x3F000000u);   // (0.5, 0.5)
    const ull nh2 = pack2u(0xBF000000u, 0xBF000000u);   // (-0.5, -0.5)

    ull a3[3];
#pragma unroll
    for (int g3 = 0; g3 < 3; g3++) {
        ull a9[3];
#pragma unroll
        for (int g9 = 0; g9 < 3; g9++) {
            ull ch[3];
#pragma unroll
            for (int cc = 0; cc < 3; cc++) {
                const int c = g3 * 9 + g9 * 3 + cc;
                ull rr[3];
#pragma unroll
                for (int ki = 0; ki < 3; ki++) {
                    const int row = c * 3 + ki;
                    float2 u = t2[row * (PITCH / 2) + p];       // t0, t1
                    float2 v = t2[row * (PITCH / 2) + p + 1];   // t2, t3
                    float4 wv = wp[row];
                    float m  = u.y * v.x;          // t1*t2, shared between pixels
                    float p0 = u.x * m;            // t0t1t2
                    float p1 = m * v.y;            // t1t2t3
                    // scalar folded leaf maj3 (weights pre-scaled by 0.5)
                    float ra = u.x * wv.x + u.y * wv.y + v.x * wv.z - p0 * wv.w;
                    float rb = u.y * wv.x + v.x * wv.y + v.y * wv.z - p1 * wv.w;
                    rr[ki] = pack2f(ra, rb);       // lanes: (col 2p | col 2p+1)
                }
                ch[cc] = maj3p(rr[0], rr[1], rr[2], h2, nh2);
            }
            a9[g9] = maj3p(ch[0], ch[1], ch[2], h2, nh2);
        }
        a3[g3] = maj3p(a9[0], a9[1], a9[2], h2, nh2);
    }
    ull res = maj3p(a3[0], a3[1], a3[2], h2, nh2);

    const int oc = ocg * 4 + ol;
    ull* op = reinterpret_cast<ull*>(out + (((size_t)n * OC + oc) * HH + h) * WW);
    op[p] = res;   // stores (col 2p, col 2p+1)
}

extern "C" void kernel_launch(void* const* d_in, const int* in_sizes, int n_in,
                              void* d_out, int out_size) {
    const float* x = (const float*)d_in[0];
    const float* w = (const float*)d_in[1];
    float* out = (float*)d_out;

    dim3 grid(HH, OC / 4, NB);
    sconv_kernel<<<grid, 128>>>(x, w, out);
}